// round 14
// baseline (speedup 1.0000x reference)
#include <cuda_runtime.h>
#include <cuda_bf16.h>
#include <cstdint>

// high_order_residual (braq, order=2), row-wise over (11008, 4096).
// R14 (= R13 + missing <cstdint>): persistent CTAs (grid=444, strided rows)
// with cp.async staging of each row's x+mask into shared memory. The next
// row's HBM traffic is issued BEFORE the current row's reductions, so DRAM
// never drains during the barrier-serialized phases. Math identical to
// R11/R12 (copysign, closed-form mean1) -> rel_err 2.4e-4.

#define ROW_LEN 4096
#define NTHREADS 256
#define CHUNKS 4          // float4/int4 chunks per thread (4*4 = 16 elems)
#define GRID_CTAS 444     // 148 SMs x 3 CTAs -> one full wave

__device__ __forceinline__ void cp_async16(unsigned int saddr, const void* gaddr) {
    asm volatile("cp.async.cg.shared.global [%0], [%1], 16;\n"
                 :: "r"(saddr), "l"(gaddr));
}
__device__ __forceinline__ void cp_async_commit() {
    asm volatile("cp.async.commit_group;\n");
}
__device__ __forceinline__ void cp_async_wait0() {
    asm volatile("cp.async.wait_group 0;\n");
}

// Two-value block reduction, ONE __syncthreads. sb >= 16 floats, unique
// per call site. All threads end with identical (deterministic) sums.
__device__ __forceinline__ void block_reduce2(float& a, float& b, float* sb) {
#pragma unroll
    for (int o = 16; o > 0; o >>= 1) {
        a += __shfl_down_sync(0xFFFFFFFFu, a, o);
        b += __shfl_down_sync(0xFFFFFFFFu, b, o);
    }
    const int w = threadIdx.x >> 5;
    if ((threadIdx.x & 31) == 0) { sb[2 * w] = a; sb[2 * w + 1] = b; }
    __syncthreads();
    float ra = sb[0], rb = sb[1];
#pragma unroll
    for (int i = 1; i < 8; i++) { ra += sb[2 * i]; rb += sb[2 * i + 1]; }
    a = ra;
    b = rb;
}

// One-value block reduction, ONE __syncthreads.
__device__ __forceinline__ void block_reduce1(float& a, float* sb) {
#pragma unroll
    for (int o = 16; o > 0; o >>= 1)
        a += __shfl_down_sync(0xFFFFFFFFu, a, o);
    const int w = threadIdx.x >> 5;
    if ((threadIdx.x & 31) == 0) sb[w] = a;
    __syncthreads();
    float ra = sb[0];
#pragma unroll
    for (int i = 1; i < 8; i++) ra += sb[i];
    a = ra;
}

__global__ __launch_bounds__(NTHREADS) void braq_order2_kernel(
    const float* __restrict__ x,
    const int* __restrict__ mask,
    float* __restrict__ out,
    int rows)
{
    __shared__ float4 sx[ROW_LEN / 4];   // 16 KB staged x row
    __shared__ int4   smk[ROW_LEN / 4];  // 16 KB staged mask row
    __shared__ float sred0[16];
    __shared__ float sred1[16];
    __shared__ float sred2[8];

    const int tid = threadIdx.x;
    const unsigned int sx_base =
        (unsigned int)__cvta_generic_to_shared(sx);
    const unsigned int smk_base =
        (unsigned int)__cvta_generic_to_shared(smk);

    int row = blockIdx.x;

    // ---- Prologue: prefetch first row ----
    if (row < rows) {
        const float4* xp = reinterpret_cast<const float4*>(x + (size_t)row * ROW_LEN);
        const int4*   mp = reinterpret_cast<const int4*>(mask + (size_t)row * ROW_LEN);
#pragma unroll
        for (int k = 0; k < CHUNKS; k++) {
            const int idx = tid + k * NTHREADS;
            cp_async16(sx_base + idx * 16, xp + idx);
            cp_async16(smk_base + idx * 16, mp + idx);
        }
    }
    cp_async_commit();

    while (row < rows) {
        // ---- Buffer ready ----
        cp_async_wait0();
        __syncthreads();

        // ---- smem -> regs, first-pass stats (cnt, sum(xm)) ----
        float v[16];    // xm (preserved to the store)
        float mf[16];   // mask as 0/1 float
        float cnt = 0.0f, s0 = 0.0f;
#pragma unroll
        for (int k = 0; k < CHUNKS; k++) {
            const int idx = tid + k * NTHREADS;
            const float4 xv = sx[idx];
            const int4 mw = smk[idx];
            const float m0 = mw.x ? 1.0f : 0.0f;
            const float m1 = mw.y ? 1.0f : 0.0f;
            const float m2 = mw.z ? 1.0f : 0.0f;
            const float m3 = mw.w ? 1.0f : 0.0f;
            mf[k * 4 + 0] = m0;
            mf[k * 4 + 1] = m1;
            mf[k * 4 + 2] = m2;
            mf[k * 4 + 3] = m3;
            v[k * 4 + 0] = xv.x * m0;
            v[k * 4 + 1] = xv.y * m1;
            v[k * 4 + 2] = xv.z * m2;
            v[k * 4 + 3] = xv.w * m3;
            cnt += m0 + m1 + m2 + m3;
            s0 += v[k * 4 + 0] + v[k * 4 + 1] + v[k * 4 + 2] + v[k * 4 + 3];
        }
        __syncthreads();   // all threads done reading smem buffer

        // ---- Issue next row's HBM traffic NOW (overlaps everything below) ----
        const int next = row + GRID_CTAS;
        if (next < rows) {
            const float4* xp = reinterpret_cast<const float4*>(x + (size_t)next * ROW_LEN);
            const int4*   mp = reinterpret_cast<const int4*>(mask + (size_t)next * ROW_LEN);
#pragma unroll
            for (int k = 0; k < CHUNKS; k++) {
                const int idx = tid + k * NTHREADS;
                cp_async16(sx_base + idx * 16, xp + idx);
                cp_async16(smk_base + idx * 16, mp + idx);
            }
        }
        cp_async_commit();

        // ---- Reduction 1: cnt, s0 ----
        block_reduce2(cnt, s0, sred0);
        const float inv_cnt = 1.0f / fmaxf(cnt, 1.0f);
        const float mean0 = s0 * inv_cnt;   // 0 when cnt==0 (s0==0 too)

        // ---- Iteration 0: reduce (sum|c0|, sum sign(c0)) ----
        float a0 = 0.0f, d0 = 0.0f;
#pragma unroll
        for (int i = 0; i < 16; i++) {
            const float c0 = (v[i] - mean0) * mf[i];
            a0 += fabsf(c0);
            d0 += copysignf(mf[i], c0);    // +-1 inside mask, +-0 outside
        }
        block_reduce2(a0, d0, sred1);
        const float scale0 = a0 * inv_cnt;

        // Closed-form mean1:
        //   sum(residual1) = s0 - sum(binary0*m)
        //   sum(binary0*m) = scale0 * d0 + cnt * mean0
        const float sum_b0 = scale0 * d0 + cnt * mean0;
        const float mean1 = (s0 - sum_b0) * inv_cnt;

        // ---- Iteration 1: recompute c0 -> binary0 -> c1; reduce sum|c1| ----
        float a1 = 0.0f;
#pragma unroll
        for (int i = 0; i < 16; i++) {
            const float c0 = (v[i] - mean0) * mf[i];
            const float b0m = (copysignf(scale0, c0) + mean0) * mf[i];
            const float c1 = (v[i] - b0m - mean1) * mf[i];
            a1 += fabsf(c1);
        }
        block_reduce1(a1, sred2);
        const float scale1 = a1 * inv_cnt;

        // ---- Recompute + store: out = binary0*m + binary1*m ----
        float4* op = reinterpret_cast<float4*>(out + (size_t)row * ROW_LEN);
#pragma unroll
        for (int k = 0; k < CHUNKS; k++) {
            const int idx = tid + k * NTHREADS;
            float4 o;
            float* oc = &o.x;
#pragma unroll
            for (int j = 0; j < 4; j++) {
                const int i = k * 4 + j;
                const float c0 = (v[i] - mean0) * mf[i];
                const float b0m = (copysignf(scale0, c0) + mean0) * mf[i];
                const float c1 = (v[i] - b0m - mean1) * mf[i];
                const float b1m = (copysignf(scale1, c1) + mean1) * mf[i];
                oc[j] = b0m + b1m;
            }
            op[idx] = o;
        }

        row = next;
    }
}

extern "C" void kernel_launch(void* const* d_in, const int* in_sizes, int n_in,
                              void* d_out, int out_size) {
    const float* x = (const float*)d_in[0];
    const int* mask = (const int*)d_in[1];
    float* out = (float*)d_out;

    const int rows = in_sizes[0] / ROW_LEN;   // 11008
    const int grid = (rows < GRID_CTAS) ? rows : GRID_CTAS;
    braq_order2_kernel<<<grid, NTHREADS>>>(x, mask, out, rows);
}

// round 15
// speedup vs baseline: 1.0011x; 1.0011x over previous
#include <cuda_runtime.h>
#include <cuda_bf16.h>
#include <cstdint>

// high_order_residual (braq, order=2), row-wise over (11008, 4096).
// R15: persistent CTAs + cp.async staging (R14) with DYNAMIC row dispatch
// via a global atomic counter (reset by a tiny kernel each launch), fixing
// the static-schedule tail that cost R14 ~11us of wall-clock vs its ncu dur.

#define ROW_LEN 4096
#define NTHREADS 256
#define CHUNKS 4          // float4/int4 chunks per thread (4*4 = 16 elems)
#define GRID_CTAS 456     // 152 SMs x 3 CTAs

__device__ int g_row_ctr;

__global__ void reset_ctr_kernel() { g_row_ctr = 0; }

__device__ __forceinline__ void cp_async16(unsigned int saddr, const void* gaddr) {
    asm volatile("cp.async.cg.shared.global [%0], [%1], 16;\n"
                 :: "r"(saddr), "l"(gaddr));
}
__device__ __forceinline__ void cp_async_commit() {
    asm volatile("cp.async.commit_group;\n");
}
__device__ __forceinline__ void cp_async_wait0() {
    asm volatile("cp.async.wait_group 0;\n");
}

// Two-value block reduction, ONE __syncthreads. sb >= 16 floats, unique
// per call site. All threads end with identical (deterministic) sums.
__device__ __forceinline__ void block_reduce2(float& a, float& b, float* sb) {
#pragma unroll
    for (int o = 16; o > 0; o >>= 1) {
        a += __shfl_down_sync(0xFFFFFFFFu, a, o);
        b += __shfl_down_sync(0xFFFFFFFFu, b, o);
    }
    const int w = threadIdx.x >> 5;
    if ((threadIdx.x & 31) == 0) { sb[2 * w] = a; sb[2 * w + 1] = b; }
    __syncthreads();
    float ra = sb[0], rb = sb[1];
#pragma unroll
    for (int i = 1; i < 8; i++) { ra += sb[2 * i]; rb += sb[2 * i + 1]; }
    a = ra;
    b = rb;
}

// One-value block reduction, ONE __syncthreads.
__device__ __forceinline__ void block_reduce1(float& a, float* sb) {
#pragma unroll
    for (int o = 16; o > 0; o >>= 1)
        a += __shfl_down_sync(0xFFFFFFFFu, a, o);
    const int w = threadIdx.x >> 5;
    if ((threadIdx.x & 31) == 0) sb[w] = a;
    __syncthreads();
    float ra = sb[0];
#pragma unroll
    for (int i = 1; i < 8; i++) ra += sb[i];
    a = ra;
}

__global__ __launch_bounds__(NTHREADS) void braq_order2_kernel(
    const float* __restrict__ x,
    const int* __restrict__ mask,
    float* __restrict__ out,
    int rows)
{
    __shared__ float4 sx[ROW_LEN / 4];   // 16 KB staged x row
    __shared__ int4   smk[ROW_LEN / 4];  // 16 KB staged mask row
    __shared__ float sred0[16];
    __shared__ float sred1[16];
    __shared__ float sred2[8];
    __shared__ int s_next;

    const int tid = threadIdx.x;
    const unsigned int sx_base =
        (unsigned int)__cvta_generic_to_shared(sx);
    const unsigned int smk_base =
        (unsigned int)__cvta_generic_to_shared(smk);

    // ---- Claim first row ----
    if (tid == 0) s_next = atomicAdd(&g_row_ctr, 1);
    __syncthreads();
    int row = s_next;

    // ---- Prologue: prefetch first row ----
    if (row < rows) {
        const float4* xp = reinterpret_cast<const float4*>(x + (size_t)row * ROW_LEN);
        const int4*   mp = reinterpret_cast<const int4*>(mask + (size_t)row * ROW_LEN);
#pragma unroll
        for (int k = 0; k < CHUNKS; k++) {
            const int idx = tid + k * NTHREADS;
            cp_async16(sx_base + idx * 16, xp + idx);
            cp_async16(smk_base + idx * 16, mp + idx);
        }
    }
    cp_async_commit();

    while (row < rows) {
        // ---- Buffer ready ----
        cp_async_wait0();
        __syncthreads();

        // ---- smem -> regs, first-pass stats (cnt, sum(xm)) ----
        float v[16];    // xm (preserved to the store)
        float mf[16];   // mask as 0/1 float
        float cnt = 0.0f, s0 = 0.0f;
#pragma unroll
        for (int k = 0; k < CHUNKS; k++) {
            const int idx = tid + k * NTHREADS;
            const float4 xv = sx[idx];
            const int4 mw = smk[idx];
            const float m0 = mw.x ? 1.0f : 0.0f;
            const float m1 = mw.y ? 1.0f : 0.0f;
            const float m2 = mw.z ? 1.0f : 0.0f;
            const float m3 = mw.w ? 1.0f : 0.0f;
            mf[k * 4 + 0] = m0;
            mf[k * 4 + 1] = m1;
            mf[k * 4 + 2] = m2;
            mf[k * 4 + 3] = m3;
            v[k * 4 + 0] = xv.x * m0;
            v[k * 4 + 1] = xv.y * m1;
            v[k * 4 + 2] = xv.z * m2;
            v[k * 4 + 3] = xv.w * m3;
            cnt += m0 + m1 + m2 + m3;
            s0 += v[k * 4 + 0] + v[k * 4 + 1] + v[k * 4 + 2] + v[k * 4 + 3];
        }

        // ---- Claim next row (overlaps with nothing critical; barrier also
        //      closes the smem-buffer read phase) ----
        if (tid == 0) s_next = atomicAdd(&g_row_ctr, 1);
        __syncthreads();   // buffer reads done + s_next visible
        const int next = s_next;

        // ---- Issue next row's HBM traffic NOW (overlaps everything below) ----
        if (next < rows) {
            const float4* xp = reinterpret_cast<const float4*>(x + (size_t)next * ROW_LEN);
            const int4*   mp = reinterpret_cast<const int4*>(mask + (size_t)next * ROW_LEN);
#pragma unroll
            for (int k = 0; k < CHUNKS; k++) {
                const int idx = tid + k * NTHREADS;
                cp_async16(sx_base + idx * 16, xp + idx);
                cp_async16(smk_base + idx * 16, mp + idx);
            }
        }
        cp_async_commit();

        // ---- Reduction 1: cnt, s0 ----
        block_reduce2(cnt, s0, sred0);
        const float inv_cnt = 1.0f / fmaxf(cnt, 1.0f);
        const float mean0 = s0 * inv_cnt;   // 0 when cnt==0 (s0==0 too)

        // ---- Iteration 0: reduce (sum|c0|, sum sign(c0)) ----
        float a0 = 0.0f, d0 = 0.0f;
#pragma unroll
        for (int i = 0; i < 16; i++) {
            const float c0 = (v[i] - mean0) * mf[i];
            a0 += fabsf(c0);
            d0 += copysignf(mf[i], c0);    // +-1 inside mask, +-0 outside
        }
        block_reduce2(a0, d0, sred1);
        const float scale0 = a0 * inv_cnt;

        // Closed-form mean1:
        //   sum(residual1) = s0 - sum(binary0*m)
        //   sum(binary0*m) = scale0 * d0 + cnt * mean0
        const float sum_b0 = scale0 * d0 + cnt * mean0;
        const float mean1 = (s0 - sum_b0) * inv_cnt;

        // ---- Iteration 1: recompute c0 -> binary0 -> c1; reduce sum|c1| ----
        float a1 = 0.0f;
#pragma unroll
        for (int i = 0; i < 16; i++) {
            const float c0 = (v[i] - mean0) * mf[i];
            const float b0m = (copysignf(scale0, c0) + mean0) * mf[i];
            const float c1 = (v[i] - b0m - mean1) * mf[i];
            a1 += fabsf(c1);
        }
        block_reduce1(a1, sred2);
        const float scale1 = a1 * inv_cnt;

        // ---- Recompute + store: out = binary0*m + binary1*m ----
        float4* op = reinterpret_cast<float4*>(out + (size_t)row * ROW_LEN);
#pragma unroll
        for (int k = 0; k < CHUNKS; k++) {
            const int idx = tid + k * NTHREADS;
            float4 o;
            float* oc = &o.x;
#pragma unroll
            for (int j = 0; j < 4; j++) {
                const int i = k * 4 + j;
                const float c0 = (v[i] - mean0) * mf[i];
                const float b0m = (copysignf(scale0, c0) + mean0) * mf[i];
                const float c1 = (v[i] - b0m - mean1) * mf[i];
                const float b1m = (copysignf(scale1, c1) + mean1) * mf[i];
                oc[j] = b0m + b1m;
            }
            op[idx] = o;
        }

        row = next;
    }
}

extern "C" void kernel_launch(void* const* d_in, const int* in_sizes, int n_in,
                              void* d_out, int out_size) {
    const float* x = (const float*)d_in[0];
    const int* mask = (const int*)d_in[1];
    float* out = (float*)d_out;

    const int rows = in_sizes[0] / ROW_LEN;   // 11008
    const int grid = (rows < GRID_CTAS) ? rows : GRID_CTAS;
    reset_ctr_kernel<<<1, 1>>>();
    braq_order2_kernel<<<grid, NTHREADS>>>(x, mask, out, rows);
}

// round 16
// speedup vs baseline: 1.0937x; 1.0925x over previous
#include <cuda_runtime.h>
#include <cuda_bf16.h>
#include <cstdint>

// high_order_residual (braq, order=2), row-wise over (11008, 4096).
// One CTA per row (grid=11008), 256 threads x 16 elements, single HBM pass.
// Mask arrives as int32 words (nonzero = true).
//
// R16: minimal live state. mf[i] carries BOTH the mask (|mf| in {0,1}) and,
// after iteration 0, sign(centered0) in its sign bit. v[] is overwritten
// with centered1. No acc[] array, no recompute chains -> ~52-56 regs,
// 5 CTAs/SM, without any launch-bounds clamp.

#define ROW_LEN 4096
#define NTHREADS 256
#define CHUNKS 4          // float4/int4 chunks per thread (4*4 = 16 elems)

// Two-value block reduction, ONE __syncthreads. sb >= 16 floats, unique
// per call site. All threads end with identical (deterministic) sums.
__device__ __forceinline__ void block_reduce2(float& a, float& b, float* sb) {
#pragma unroll
    for (int o = 16; o > 0; o >>= 1) {
        a += __shfl_down_sync(0xFFFFFFFFu, a, o);
        b += __shfl_down_sync(0xFFFFFFFFu, b, o);
    }
    const int w = threadIdx.x >> 5;
    if ((threadIdx.x & 31) == 0) { sb[2 * w] = a; sb[2 * w + 1] = b; }
    __syncthreads();
    float ra = sb[0], rb = sb[1];
#pragma unroll
    for (int i = 1; i < 8; i++) { ra += sb[2 * i]; rb += sb[2 * i + 1]; }
    a = ra;
    b = rb;
}

// One-value block reduction, ONE __syncthreads.
__device__ __forceinline__ void block_reduce1(float& a, float* sb) {
#pragma unroll
    for (int o = 16; o > 0; o >>= 1)
        a += __shfl_down_sync(0xFFFFFFFFu, a, o);
    const int w = threadIdx.x >> 5;
    if ((threadIdx.x & 31) == 0) sb[w] = a;
    __syncthreads();
    float ra = sb[0];
#pragma unroll
    for (int i = 1; i < 8; i++) ra += sb[i];
    a = ra;
}

__global__ __launch_bounds__(NTHREADS) void braq_order2_kernel(
    const float* __restrict__ x,
    const int* __restrict__ mask,
    float* __restrict__ out)
{
    __shared__ float sred0[16];
    __shared__ float sred1[16];
    __shared__ float sred2[8];

    const int row = blockIdx.x;
    const int tid = threadIdx.x;
    const size_t base = (size_t)row * ROW_LEN;

    const float4* __restrict__ xp = reinterpret_cast<const float4*>(x + base);
    const int4*   __restrict__ mp = reinterpret_cast<const int4*>(mask + base);

    float v[16];    // xm -> centered1
    float mf[16];   // mask 0/1; after iter0: sign(c0) in the sign bit, |mf| = mask

    // ---- Load + first-pass stats: cnt, sum(xm) ----
    float cnt = 0.0f, s0 = 0.0f;
#pragma unroll
    for (int k = 0; k < CHUNKS; k++) {
        const int idx = tid + k * NTHREADS;
        const float4 xv = xp[idx];
        const int4 mw = mp[idx];
        const float m0 = mw.x ? 1.0f : 0.0f;
        const float m1 = mw.y ? 1.0f : 0.0f;
        const float m2 = mw.z ? 1.0f : 0.0f;
        const float m3 = mw.w ? 1.0f : 0.0f;
        mf[k * 4 + 0] = m0;
        mf[k * 4 + 1] = m1;
        mf[k * 4 + 2] = m2;
        mf[k * 4 + 3] = m3;
        v[k * 4 + 0] = xv.x * m0;
        v[k * 4 + 1] = xv.y * m1;
        v[k * 4 + 2] = xv.z * m2;
        v[k * 4 + 3] = xv.w * m3;
        cnt += m0 + m1 + m2 + m3;
        s0 += v[k * 4 + 0] + v[k * 4 + 1] + v[k * 4 + 2] + v[k * 4 + 3];
    }

    block_reduce2(cnt, s0, sred0);
    const float inv_cnt = 1.0f / fmaxf(cnt, 1.0f);
    const float mean0 = s0 * inv_cnt;   // 0 when cnt==0 (s0==0 too)

    // ---- Iteration 0: reduce (sum|c0|, sum sign(c0)); stash sign0 in mf ----
    float a0 = 0.0f, d0 = 0.0f;
#pragma unroll
    for (int i = 0; i < 16; i++) {
        const float c0 = (v[i] - mean0) * mf[i];
        a0 += fabsf(c0);
        const float smf = copysignf(mf[i], c0);   // +-1 in mask, +-0 outside
        d0 += smf;
        mf[i] = smf;                              // sign(c0) stashed in sign bit
    }
    block_reduce2(a0, d0, sred1);
    const float scale0 = a0 * inv_cnt;

    // Closed-form mean1:
    //   sum(residual1) = s0 - sum(binary0*m)
    //   sum(binary0*m) = scale0 * d0 + cnt * mean0
    const float sum_b0 = scale0 * d0 + cnt * mean0;
    const float mean1 = (s0 - sum_b0) * inv_cnt;

    // ---- Iteration 1: b0m from stashed sign; c1 -> v; reduce sum|c1| ----
    float a1 = 0.0f;
#pragma unroll
    for (int i = 0; i < 16; i++) {
        const float am = fabsf(mf[i]);            // mask 0/1
        const float b0m = (copysignf(scale0, mf[i]) + mean0) * am;
        const float c1 = (v[i] - b0m - mean1) * am;
        v[i] = c1;
        a1 += fabsf(c1);
    }
    block_reduce1(a1, sred2);
    const float scale1 = a1 * inv_cnt;

    // ---- Store: out = binary0*m + binary1*m ----
    float4* __restrict__ op = reinterpret_cast<float4*>(out + base);
#pragma unroll
    for (int k = 0; k < CHUNKS; k++) {
        const int idx = tid + k * NTHREADS;
        float4 o;
        float* oc = &o.x;
#pragma unroll
        for (int j = 0; j < 4; j++) {
            const int i = k * 4 + j;
            const float am = fabsf(mf[i]);
            const float b0m = (copysignf(scale0, mf[i]) + mean0) * am;
            const float b1m = (copysignf(scale1, v[i]) + mean1) * am;
            oc[j] = b0m + b1m;
        }
        op[idx] = o;
    }
}

extern "C" void kernel_launch(void* const* d_in, const int* in_sizes, int n_in,
                              void* d_out, int out_size) {
    const float* x = (const float*)d_in[0];
    const int* mask = (const int*)d_in[1];
    float* out = (float*)d_out;

    const int rows = in_sizes[0] / ROW_LEN;   // 11008
    braq_order2_kernel<<<rows, NTHREADS>>>(x, mask, out);
}